// round 1
// baseline (speedup 1.0000x reference)
#include <cuda_runtime.h>
#include <cuda_bf16.h>
#include <cstdint>

// ---------------------------------------------------------------------------
// CloudCrop: cylinder query + gather + 2-layer MLP (BN folded) + maxpool
// B=4, N=1024, NSAMPLE=32, C_IN=512, C_MID=256, C_OUT=256
// ---------------------------------------------------------------------------

#define Bc 4
#define Nc 1024
#define NS 32
#define CIN 512
#define CMID 256
#define COUT 256
#define C0 515            // 3 + CIN
#define C0P 516           // padded to multiple of 4
#define Q1 129            // C0P / 4 quads for layer 1
#define Q2 64             // CMID / 4 quads for layer 2
#define RADIUSf 0.05f
#define HMINf (-0.02f)
#define HMAXf 0.04f

// scratch (allocation-free: __device__ globals)
__device__ float d_featT[Bc * Nc * CIN];        // [b][n][c]  8 MB
__device__ int   d_idx[Bc * Nc * NS];           // neighbor indices
__device__ float d_rel[Bc * Nc * NS * 3];       // rotated rel coords / RADIUS
__device__ float d_w1q[Q1 * 1024];              // [q][o][4]  folded+permuted
__device__ float d_w2q[Q2 * 1024];              // [q][o][4]  folded
__device__ float d_bias1[CMID];
__device__ float d_bias2[COUT];

// ---------------------------------------------------------------------------
// Prep: fold BN into weights; permute layer-1 columns so that
//   xs[c] for c<512  = feature channel c   (orig w1 column c+3)
//   xs[512..514]     = rel components       (orig w1 columns 0..2)
//   xs[515]          = 0 pad
// Quad-pack: w_q[q*1024 + o*4 + r] = w[o][4q+r]
// ---------------------------------------------------------------------------
__global__ void prep_weights(const float* __restrict__ w1,
                             const float* __restrict__ g1, const float* __restrict__ b1,
                             const float* __restrict__ m1, const float* __restrict__ v1,
                             const float* __restrict__ w2,
                             const float* __restrict__ g2, const float* __restrict__ b2,
                             const float* __restrict__ m2, const float* __restrict__ v2)
{
    int i = blockIdx.x * blockDim.x + threadIdx.x;
    if (i < Q1 * 1024) {
        int q = i >> 10, rem = i & 1023;
        int o = rem >> 2, r = rem & 3;
        int c = q * 4 + r;                      // permuted column
        float s = g1[o] * rsqrtf(v1[o] + 1e-5f);
        float val = 0.f;
        if (c < 512)       val = w1[o * C0 + (c + 3)];
        else if (c < 515)  val = w1[o * C0 + (c - 512)];
        d_w1q[i] = val * s;
    }
    int j = i - Q1 * 1024;
    if (j >= 0 && j < Q2 * 1024) {
        int q = j >> 10, rem = j & 1023;
        int o = rem >> 2, r = rem & 3;
        int c = q * 4 + r;
        float s = g2[o] * rsqrtf(v2[o] + 1e-5f);
        d_w2q[j] = w2[o * CMID + c] * s;
    }
    if (i < CMID) {
        float s1 = g1[i] * rsqrtf(v1[i] + 1e-5f);
        d_bias1[i] = b1[i] - m1[i] * s1;
        float s2 = g2[i] * rsqrtf(v2[i] + 1e-5f);
        d_bias2[i] = b2[i] - m2[i] * s2;
    }
}

// ---------------------------------------------------------------------------
// Transpose seed_features [B,512,N] -> featT [B,N,512] (point-major)
// ---------------------------------------------------------------------------
__global__ void transpose_feat(const float* __restrict__ f)
{
    __shared__ float tile[32][33];
    int b  = blockIdx.z;
    int c0 = blockIdx.y * 32;
    int n0 = blockIdx.x * 32;
    int tx = threadIdx.x, ty = threadIdx.y;
    const float* src = f + (size_t)b * CIN * Nc;
    #pragma unroll
    for (int k = 0; k < 32; k += 8)
        tile[ty + k][tx] = src[(c0 + ty + k) * Nc + n0 + tx];
    __syncthreads();
    float* dst = d_featT + (size_t)b * Nc * CIN;
    #pragma unroll
    for (int k = 0; k < 32; k += 8)
        dst[(n0 + ty + k) * CIN + c0 + tx] = tile[tx][ty + k];
}

// ---------------------------------------------------------------------------
// Cylinder query: one warp per (b,n). Collect first 32 masked indices
// (ascending m, matching stable argsort of ~mask), pad with idx[0]
// (=0 when count==0). Also emit rotated rel coords / RADIUS.
// ---------------------------------------------------------------------------
__global__ void cylinder_query(const float* __restrict__ xyz,
                               const float* __restrict__ rot)
{
    __shared__ int sidx[4][NS];
    int w    = threadIdx.x >> 5;
    int lane = threadIdx.x & 31;
    int p = blockIdx.x * 4 + w;           // global point id
    int b = p >> 10, n = p & 1023;

    const float* X = xyz + (size_t)b * Nc * 3;
    float cx = X[n * 3 + 0], cy = X[n * 3 + 1], cz = X[n * 3 + 2];
    const float* R = rot + (size_t)p * 9;
    float r00 = R[0], r01 = R[1], r02 = R[2];
    float r10 = R[3], r11 = R[4], r12 = R[5];
    float r20 = R[6], r21 = R[7], r22 = R[8];
    const float R2 = RADIUSf * RADIUSf;

    int cnt = 0;
    for (int m0 = 0; m0 < Nc; m0 += 32) {
        int m = m0 + lane;
        float dx = X[m * 3 + 0] - cx;
        float dy = X[m * 3 + 1] - cy;
        float dz = X[m * 3 + 2] - cz;
        float xr = r00 * dx + r01 * dy + r02 * dz;
        float yr = r10 * dx + r11 * dy + r12 * dz;
        float zr = r20 * dx + r21 * dy + r22 * dz;
        bool mk = (yr * yr + zr * zr < R2) && (xr > HMINf) && (xr < HMAXf);
        unsigned bal = __ballot_sync(0xffffffffu, mk);
        int pre = __popc(bal & ((1u << lane) - 1u));
        int slot = cnt + pre;
        if (mk && slot < NS) sidx[w][slot] = m;
        cnt += __popc(bal);
        if (cnt >= NS) break;
    }
    __syncwarp();
    int c32 = cnt < NS ? cnt : NS;
    int pad = (cnt > 0) ? sidx[w][0] : 0;
    int j = (lane < c32) ? sidx[w][lane] : pad;

    d_idx[p * NS + lane] = j;
    float dx = X[j * 3 + 0] - cx;
    float dy = X[j * 3 + 1] - cy;
    float dz = X[j * 3 + 2] - cz;
    // einsum('bnsj,bnjk->bnsk'): out[k] = sum_j d[j] * R[j][k]
    float inv = 1.0f / RADIUSf;
    d_rel[(p * NS + lane) * 3 + 0] = (dx * r00 + dy * r10 + dz * r20) * inv;
    d_rel[(p * NS + lane) * 3 + 1] = (dx * r01 + dy * r11 + dz * r21) * inv;
    d_rel[(p * NS + lane) * 3 + 2] = (dx * r02 + dy * r12 + dz * r22) * inv;
}

// ---------------------------------------------------------------------------
// Fused MLP: one CTA per (b,n). Stage x[32][516] in smem, two GEMM layers
// with BN-folded weights, relu, maxpool over the 32 samples.
// Thread t: channels (t&127) and (t&127)+128, samples [(t>>7)*16, +16).
// ---------------------------------------------------------------------------
__global__ void __launch_bounds__(256)
fused_mlp(float* __restrict__ out)
{
    extern __shared__ float sm[];
    float* xsF = sm;                 // 32 rows * 516 floats
    float* red = sm + 32 * C0P;      // 256 floats (cross-half max reduce)
    __shared__ int lidx[NS];

    int p = blockIdx.x;
    int b = p >> 10, n = p & 1023;
    int tid = threadIdx.x;
    int oo = tid & 127;
    int sh = tid >> 7;               // 0 or 1: sample half
    int srow = sh * 16;

    if (tid < NS) {
        lidx[tid] = d_idx[p * NS + tid];
        xsF[tid * C0P + 515] = 0.f;  // pad column
    }
    __syncthreads();

    // stage features: xs[s][0..511] = featT[b][idx[s]][0..511]  (float4 coalesced)
    const float4* ftb4 = reinterpret_cast<const float4*>(d_featT + (size_t)b * Nc * CIN);
    for (int i = tid; i < NS * 128; i += 256) {
        int s = i >> 7, c4 = i & 127;
        float4 v = ftb4[lidx[s] * 128 + c4];
        *reinterpret_cast<float4*>(xsF + s * C0P + (c4 << 2)) = v;
    }
    // stage rel at columns 512..514
    if (tid < NS * 3) {
        int s = tid / 3, k = tid - s * 3;
        xsF[s * C0P + 512 + k] = d_rel[p * (NS * 3) + tid];
    }
    __syncthreads();

    float acc0[16], acc1[16];
    #pragma unroll
    for (int j = 0; j < 16; j++) { acc0[j] = 0.f; acc1[j] = 0.f; }

    // ---- layer 1: K = 516 (129 quads) ----
    const float4* w1q4 = reinterpret_cast<const float4*>(d_w1q);
    #pragma unroll 2
    for (int q = 0; q < Q1; q++) {
        float4 wa = w1q4[q * 256 + oo];
        float4 wb = w1q4[q * 256 + oo + 128];
        #pragma unroll
        for (int j = 0; j < 16; j++) {
            float4 xv = reinterpret_cast<const float4*>(xsF + (srow + j) * C0P)[q];
            acc0[j] += wa.x * xv.x; acc0[j] += wa.y * xv.y;
            acc0[j] += wa.z * xv.z; acc0[j] += wa.w * xv.w;
            acc1[j] += wb.x * xv.x; acc1[j] += wb.y * xv.y;
            acc1[j] += wb.z * xv.z; acc1[j] += wb.w * xv.w;
        }
    }

    float bi0 = d_bias1[oo];
    float bi1 = d_bias1[oo + 128];
    __syncthreads();                 // all xs reads done; reuse region for y1

    float* ysF = sm;                 // 32 rows * 256 floats (overlays xs)
    #pragma unroll
    for (int j = 0; j < 16; j++) {
        ysF[(srow + j) * CMID + oo]       = fmaxf(acc0[j] + bi0, 0.f);
        ysF[(srow + j) * CMID + oo + 128] = fmaxf(acc1[j] + bi1, 0.f);
    }
    __syncthreads();

    #pragma unroll
    for (int j = 0; j < 16; j++) { acc0[j] = 0.f; acc1[j] = 0.f; }

    // ---- layer 2: K = 256 (64 quads) ----
    const float4* w2q4 = reinterpret_cast<const float4*>(d_w2q);
    #pragma unroll 2
    for (int q = 0; q < Q2; q++) {
        float4 wa = w2q4[q * 256 + oo];
        float4 wb = w2q4[q * 256 + oo + 128];
        #pragma unroll
        for (int j = 0; j < 16; j++) {
            float4 xv = reinterpret_cast<const float4*>(ysF + (srow + j) * CMID)[q];
            acc0[j] += wa.x * xv.x; acc0[j] += wa.y * xv.y;
            acc0[j] += wa.z * xv.z; acc0[j] += wa.w * xv.w;
            acc1[j] += wb.x * xv.x; acc1[j] += wb.y * xv.y;
            acc1[j] += wb.z * xv.z; acc1[j] += wb.w * xv.w;
        }
    }

    // max over this thread's 16 samples, then bias+relu (monotone, commutes)
    float m0 = acc0[0], m1 = acc1[0];
    #pragma unroll
    for (int j = 1; j < 16; j++) { m0 = fmaxf(m0, acc0[j]); m1 = fmaxf(m1, acc1[j]); }
    float r0 = fmaxf(m0 + d_bias2[oo], 0.f);
    float r1 = fmaxf(m1 + d_bias2[oo + 128], 0.f);

    __syncthreads();                 // ys reads done before red (same buffer family)
    if (sh == 1) { red[oo] = r0; red[oo + 128] = r1; }
    __syncthreads();
    if (sh == 0) {
        float f0 = fmaxf(r0, red[oo]);
        float f1 = fmaxf(r1, red[oo + 128]);
        out[((size_t)b * COUT + oo) * Nc + n]         = f0;
        out[((size_t)b * COUT + oo + 128) * Nc + n]   = f1;
    }
}

// ---------------------------------------------------------------------------
extern "C" void kernel_launch(void* const* d_in, const int* in_sizes, int n_in,
                              void* d_out, int out_size)
{
    const float* xyz  = (const float*)d_in[0];   // (4,1024,3)
    const float* feat = (const float*)d_in[1];   // (4,512,1024)
    const float* rot  = (const float*)d_in[2];   // (4,1024,3,3)
    const float* w1   = (const float*)d_in[3];   // (256,515)
    const float* g1   = (const float*)d_in[4];
    const float* b1   = (const float*)d_in[5];
    const float* m1   = (const float*)d_in[6];
    const float* v1   = (const float*)d_in[7];
    const float* w2   = (const float*)d_in[8];   // (256,256)
    const float* g2   = (const float*)d_in[9];
    const float* b2   = (const float*)d_in[10];
    const float* m2   = (const float*)d_in[11];
    const float* v2   = (const float*)d_in[12];
    float* out = (float*)d_out;                  // (4,256,1024)

    const int SMEM_BYTES = (32 * C0P + 256) * 4; // 67072
    cudaFuncSetAttribute(fused_mlp, cudaFuncAttributeMaxDynamicSharedMemorySize, SMEM_BYTES);

    int prep_total = Q1 * 1024 + Q2 * 1024;      // 197632
    prep_weights<<<(prep_total + 255) / 256, 256>>>(w1, g1, b1, m1, v1,
                                                    w2, g2, b2, m2, v2);
    transpose_feat<<<dim3(Nc / 32, CIN / 32, Bc), dim3(32, 8)>>>(feat);
    cylinder_query<<<(Bc * Nc) / 4, 128>>>(xyz, rot);
    fused_mlp<<<Bc * Nc, 256, SMEM_BYTES>>>(out);
}

// round 4
// speedup vs baseline: 2.9873x; 2.9873x over previous
#include <cuda_runtime.h>
#include <cuda_bf16.h>
#include <cstdint>

// ---------------------------------------------------------------------------
// CloudCrop via mma.sync bf16 hi/lo split (sm_100 base target — no tcgen05).
// B=4, N=1024, NS=32, 512->256->256, maxpool over 32 samples.
// R4 fix: feature gather now applies the batch base offset (R3 read batch 0
// for all CTAs -> rel_err 0.266).
// ---------------------------------------------------------------------------

#define Bc 4
#define Nc 1024
#define NS 32
#define CIN 512
#define C0 515
#define RADIUSf 0.05f
#define HMINf (-0.02f)
#define HMAXf 0.04f

#define KC 32                 // K per chunk
#define KROWB 80              // padded A/W tile row bytes (40 bf16)
#define CH1 17                // layer-1 chunks (K=544; cols 544..575 all zero)
#define CH2 8                 // layer-2 chunks (K=256)
#define A2ROWB 528            // flat y1 row bytes (256 bf16 + 8 pad)

// smem offsets (dynamic)
#define SM_A2H   0
#define SM_A2L   67584
#define SM_A1    0            // 4 x 10240, overlays A2H (dead until L1 epilogue)
#define SM_W     135168       // 4 x 20480 (buf x {h,l})
#define SM_B1    217088
#define SM_B2    218112
#define SM_LIDX  219136
#define SMEM_TOTAL 219648

// __device__ scratch (allocation-free), 16B-aligned for cp.async/float4
__device__ __align__(16) unsigned short d_fh[Bc * Nc * CIN];   // feat hi bf16 [b][n][c]
__device__ __align__(16) unsigned short d_fl[Bc * Nc * CIN];   // feat lo
__device__ __align__(16) int            d_idx[Bc * Nc * NS];
__device__ __align__(16) float          d_rel[Bc * Nc * NS * 3];
__device__ __align__(16) unsigned short d_w1h[CH1 * 256 * 40]; // [t][o][40] padded rows
__device__ __align__(16) unsigned short d_w1l[CH1 * 256 * 40];
__device__ __align__(16) unsigned short d_w2h[CH2 * 256 * 40];
__device__ __align__(16) unsigned short d_w2l[CH2 * 256 * 40];
__device__ __align__(16) float          d_bias1[256];
__device__ __align__(16) float          d_bias2[256];

__device__ __forceinline__ void bsplit(float v, unsigned short& h, unsigned short& l) {
    __nv_bfloat16 hb = __float2bfloat16_rn(v);
    h = __bfloat16_as_ushort(hb);
    l = __bfloat16_as_ushort(__float2bfloat16_rn(v - __bfloat162float(hb)));
}
__device__ __forceinline__ uint32_t s2u(const void* p) {
    uint32_t a;
    asm("{ .reg .u64 t; cvta.to.shared.u64 t, %1; cvt.u32.u64 %0, t; }" : "=r"(a) : "l"(p));
    return a;
}
__device__ __forceinline__ void cpa16(uint32_t dst, const void* src) {
    asm volatile("cp.async.cg.shared.global [%0], [%1], 16;" :: "r"(dst), "l"(src));
}
#define CP_COMMIT()  asm volatile("cp.async.commit_group;" ::: "memory")
#define CP_WAIT0()   asm volatile("cp.async.wait_group 0;" ::: "memory")

__device__ __forceinline__ void ldsm4(uint32_t& r0, uint32_t& r1, uint32_t& r2, uint32_t& r3,
                                      uint32_t addr) {
    asm volatile("ldmatrix.sync.aligned.m8n8.x4.shared.b16 {%0,%1,%2,%3}, [%4];"
                 : "=r"(r0), "=r"(r1), "=r"(r2), "=r"(r3) : "r"(addr));
}
#define MMA(d, A, b0r, b1r) \
    asm volatile("mma.sync.aligned.m16n8k16.row.col.f32.bf16.bf16.f32 " \
                 "{%0,%1,%2,%3},{%4,%5,%6,%7},{%8,%9},{%0,%1,%2,%3};" \
                 : "+f"((d).x), "+f"((d).y), "+f"((d).z), "+f"((d).w) \
                 : "r"((A)[0]), "r"((A)[1]), "r"((A)[2]), "r"((A)[3]), \
                   "r"(b0r), "r"(b1r))

// One k16 step: acc += Ah*Wh + Ah*Wl + Al*Wh  (96 HMMA)
template<int AROW>
__device__ __forceinline__ void gemm_kstep(float4 (&acc)[4][8],
    uint32_t ah, uint32_t al, uint32_t wh, uint32_t wl)
{
    uint32_t Ah[4][4], Al[4][4], Bh[4][4], Bl[4][4];
    #pragma unroll
    for (int mt = 0; mt < 4; mt++) {
        ldsm4(Ah[mt][0], Ah[mt][1], Ah[mt][2], Ah[mt][3], ah + mt * 16 * AROW);
        ldsm4(Al[mt][0], Al[mt][1], Al[mt][2], Al[mt][3], al + mt * 16 * AROW);
    }
    #pragma unroll
    for (int p = 0; p < 4; p++) {
        ldsm4(Bh[p][0], Bh[p][1], Bh[p][2], Bh[p][3], wh + p * 16 * KROWB);
        ldsm4(Bl[p][0], Bl[p][1], Bl[p][2], Bl[p][3], wl + p * 16 * KROWB);
    }
    #pragma unroll
    for (int mt = 0; mt < 4; mt++) {
        #pragma unroll
        for (int p = 0; p < 4; p++) {
            MMA(acc[mt][2*p],   Ah[mt], Bh[p][0], Bh[p][1]);
            MMA(acc[mt][2*p],   Ah[mt], Bl[p][0], Bl[p][1]);
            MMA(acc[mt][2*p],   Al[mt], Bh[p][0], Bh[p][1]);
            MMA(acc[mt][2*p+1], Ah[mt], Bh[p][2], Bh[p][3]);
            MMA(acc[mt][2*p+1], Ah[mt], Bl[p][2], Bl[p][3]);
            MMA(acc[mt][2*p+1], Al[mt], Bh[p][2], Bh[p][3]);
        }
    }
}

// ---------------------------------------------------------------------------
// Prep: fold BN into weights, hi/lo split, padded chunked layout [t][o][40].
// Column map: c<512 -> w1 col c+3 (features); 512..514 -> w1 cols 0..2 (rel).
// ---------------------------------------------------------------------------
__global__ void prep_w(const float* __restrict__ w1,
                       const float* __restrict__ g1, const float* __restrict__ b1,
                       const float* __restrict__ m1, const float* __restrict__ v1,
                       const float* __restrict__ w2,
                       const float* __restrict__ g2, const float* __restrict__ b2,
                       const float* __restrict__ m2, const float* __restrict__ v2)
{
    int i = blockIdx.x * blockDim.x + threadIdx.x;
    const int W1E = CH1 * 256 * 40;
    const int W2E = CH2 * 256 * 40;
    if (i < W1E) {
        int t = i / 10240, rem = i % 10240, o = rem / 40, k = rem % 40;
        int c = t * KC + k;
        float val = 0.f;
        if (k < KC) {
            float s = g1[o] * rsqrtf(v1[o] + 1e-5f);
            if (c < 512)      val = w1[o * C0 + c + 3] * s;
            else if (c < 515) val = w1[o * C0 + (c - 512)] * s;
        }
        unsigned short h, l; bsplit(val, h, l);
        d_w1h[i] = h; d_w1l[i] = l;
    }
    int j = i - W1E;
    if (j >= 0 && j < W2E) {
        int t = j / 10240, rem = j % 10240, o = rem / 40, k = rem % 40;
        float val = 0.f;
        if (k < KC) {
            float s = g2[o] * rsqrtf(v2[o] + 1e-5f);
            val = w2[o * 256 + t * KC + k] * s;
        }
        unsigned short h, l; bsplit(val, h, l);
        d_w2h[j] = h; d_w2l[j] = l;
    }
    if (i < 256) {
        float s1 = g1[i] * rsqrtf(v1[i] + 1e-5f);
        d_bias1[i] = b1[i] - m1[i] * s1;
        float s2 = g2[i] * rsqrtf(v2[i] + 1e-5f);
        d_bias2[i] = b2[i] - m2[i] * s2;
    }
}

// Transpose [B,512,N] -> point-major hi/lo bf16 [B,N,512]
__global__ void transpose_feat(const float* __restrict__ f)
{
    __shared__ float tile[32][33];
    int b  = blockIdx.z;
    int c0 = blockIdx.y * 32;
    int n0 = blockIdx.x * 32;
    int tx = threadIdx.x, ty = threadIdx.y;
    const float* src = f + (size_t)b * CIN * Nc;
    #pragma unroll
    for (int k = 0; k < 32; k += 8)
        tile[ty + k][tx] = src[(c0 + ty + k) * Nc + n0 + tx];
    __syncthreads();
    size_t base = (size_t)b * Nc * CIN;
    #pragma unroll
    for (int k = 0; k < 32; k += 8) {
        float v = tile[tx][ty + k];
        unsigned short h, l; bsplit(v, h, l);
        size_t o = base + (size_t)(n0 + ty + k) * CIN + c0 + tx;
        d_fh[o] = h; d_fl[o] = l;
    }
}

__global__ void cylinder_query(const float* __restrict__ xyz,
                               const float* __restrict__ rot)
{
    __shared__ int sidx[4][NS];
    int w    = threadIdx.x >> 5;
    int lane = threadIdx.x & 31;
    int p = blockIdx.x * 4 + w;
    int b = p >> 10, n = p & 1023;

    const float* X = xyz + (size_t)b * Nc * 3;
    float cx = X[n * 3 + 0], cy = X[n * 3 + 1], cz = X[n * 3 + 2];
    const float* R = rot + (size_t)p * 9;
    float r00 = R[0], r01 = R[1], r02 = R[2];
    float r10 = R[3], r11 = R[4], r12 = R[5];
    float r20 = R[6], r21 = R[7], r22 = R[8];
    const float R2 = RADIUSf * RADIUSf;

    int cnt = 0;
    for (int m0 = 0; m0 < Nc; m0 += 32) {
        int m = m0 + lane;
        float dx = X[m * 3 + 0] - cx;
        float dy = X[m * 3 + 1] - cy;
        float dz = X[m * 3 + 2] - cz;
        float xr = r00 * dx + r01 * dy + r02 * dz;
        float yr = r10 * dx + r11 * dy + r12 * dz;
        float zr = r20 * dx + r21 * dy + r22 * dz;
        bool mk = (yr * yr + zr * zr < R2) && (xr > HMINf) && (xr < HMAXf);
        unsigned bal = __ballot_sync(0xffffffffu, mk);
        int pre = __popc(bal & ((1u << lane) - 1u));
        int slot = cnt + pre;
        if (mk && slot < NS) sidx[w][slot] = m;
        cnt += __popc(bal);
        if (cnt >= NS) break;
    }
    __syncwarp();
    int c32 = cnt < NS ? cnt : NS;
    int pad = (cnt > 0) ? sidx[w][0] : 0;
    int j = (lane < c32) ? sidx[w][lane] : pad;

    d_idx[p * NS + lane] = j;
    float dx = X[j * 3 + 0] - cx;
    float dy = X[j * 3 + 1] - cy;
    float dz = X[j * 3 + 2] - cz;
    float inv = 1.0f / RADIUSf;
    d_rel[(p * NS + lane) * 3 + 0] = (dx * r00 + dy * r10 + dz * r20) * inv;
    d_rel[(p * NS + lane) * 3 + 1] = (dx * r01 + dy * r11 + dz * r21) * inv;
    d_rel[(p * NS + lane) * 3 + 2] = (dx * r02 + dy * r12 + dz * r22) * inv;
}

// ---------------------------------------------------------------------------
// Main: one CTA = 4 points (M=128), N=256. 8 warps, 64x64 warp tiles.
// cp.async 2-deep pipeline; layer1 -> regs -> relu/split -> smem A2 -> layer2.
// ---------------------------------------------------------------------------
__global__ void __launch_bounds__(256, 1)
tc_mlp(float* __restrict__ out)
{
    extern __shared__ char smem[];
    uint32_t sb = s2u(smem);
    int tid  = threadIdx.x;
    int lane = tid & 31;
    int w    = tid >> 5;
    int mh   = w >> 2;            // m-half (0/1): rows mh*64..
    int nq   = w & 3;             // n-quarter: cols nq*64..
    int blk  = blockIdx.x;
    int bb   = blk >> 8;
    int nbase = (blk & 255) * 4;

    float* bias1s = (float*)(smem + SM_B1);
    float* bias2s = (float*)(smem + SM_B2);
    int*   lidx   = (int*)(smem + SM_LIDX);

    if (tid < 128) lidx[tid] = d_idx[blk * 128 + tid];
    bias1s[tid] = d_bias1[tid];
    bias2s[tid] = d_bias2[tid];
    __syncthreads();

    // batch-local feature bases (R4 FIX: batch offset applied)
    const char* fbh = (const char*)d_fh + (size_t)bb * (Nc * CIN * 2);
    const char* fbl = (const char*)d_fl + (size_t)bb * (Nc * CIN * 2);

    // lane-dependent fragment offsets
    uint32_t a1_off = (uint32_t)((mh * 64 + (lane & 15)) * KROWB + (lane >> 4) * 16);
    uint32_t a2_off = (uint32_t)((mh * 64 + (lane & 15)) * A2ROWB + (lane >> 4) * 16);
    uint32_t w_off  = (uint32_t)((nq * 64 + (lane & 7) + ((lane >> 4) << 3)) * KROWB
                                 + ((lane >> 3) & 1) * 16);

    // ---- prefetch helpers ----
    auto issue1 = [&](int t) {
        int buf = t & 1;
        if (t < 16) {
            #pragma unroll
            for (int it = 0; it < 4; it++) {
                int e = tid + it * 256;            // 0..1023
                int hl = e >> 9, r = (e >> 2) & 127, q = e & 3;
                uint32_t dst = sb + SM_A1 + (uint32_t)((buf * 2 + hl) * 10240 + r * KROWB + q * 16);
                const char* srcb = (hl ? fbl : fbh)
                                 + (size_t)lidx[r] * 1024 + t * 64 + q * 16;
                cpa16(dst, srcb);
            }
        } else {
            // rel chunk: zero both tiles, then 3 real columns
            uint32_t* za = (uint32_t*)(smem + SM_A1 + (buf * 2) * 10240);
            #pragma unroll
            for (int it = 0; it < 20; it++) za[tid + it * 256] = 0;
            if (tid < 128) {
                int r = tid;
                #pragma unroll
                for (int k = 0; k < 3; k++) {
                    float v = d_rel[(blk * 128 + r) * 3 + k];
                    unsigned short h, l; bsplit(v, h, l);
                    *(unsigned short*)(smem + SM_A1 + (buf * 2) * 10240     + r * KROWB + k * 2) = h;
                    *(unsigned short*)(smem + SM_A1 + (buf * 2 + 1) * 10240 + r * KROWB + k * 2) = l;
                }
            }
        }
        #pragma unroll
        for (int it = 0; it < 10; it++) {
            int e = tid + it * 256;                // 0..2559
            int hl = e >= 1280; int o16 = hl ? e - 1280 : e;
            uint32_t dst = sb + SM_W + (uint32_t)(((t & 1) * 2 + hl) * 20480 + o16 * 16);
            const char* srcb = (const char*)(hl ? d_w1l : d_w1h) + (size_t)t * 20480 + o16 * 16;
            cpa16(dst, srcb);
        }
        CP_COMMIT();
    };
    auto issue2 = [&](int t) {
        #pragma unroll
        for (int it = 0; it < 10; it++) {
            int e = tid + it * 256;
            int hl = e >= 1280; int o16 = hl ? e - 1280 : e;
            uint32_t dst = sb + SM_W + (uint32_t)(((t & 1) * 2 + hl) * 20480 + o16 * 16);
            const char* srcb = (const char*)(hl ? d_w2l : d_w2h) + (size_t)t * 20480 + o16 * 16;
            cpa16(dst, srcb);
        }
        CP_COMMIT();
    };

    float4 acc[4][8];
    #pragma unroll
    for (int mt = 0; mt < 4; mt++)
        #pragma unroll
        for (int nt = 0; nt < 8; nt++) acc[mt][nt] = make_float4(0.f, 0.f, 0.f, 0.f);

    // ================= layer 1 =================
    issue1(0);
    for (int t = 0; t < CH1; t++) {
        int buf = t & 1;
        CP_WAIT0();
        __syncthreads();
        if (t + 1 < CH1) issue1(t + 1);
        uint32_t ah = sb + SM_A1 + (uint32_t)((buf * 2    ) * 10240) + a1_off;
        uint32_t al = sb + SM_A1 + (uint32_t)((buf * 2 + 1) * 10240) + a1_off;
        uint32_t wh = sb + SM_W  + (uint32_t)((buf * 2    ) * 20480) + w_off;
        uint32_t wl = sb + SM_W  + (uint32_t)((buf * 2 + 1) * 20480) + w_off;
        gemm_kstep<KROWB>(acc, ah,      al,      wh,      wl);
        gemm_kstep<KROWB>(acc, ah + 32, al + 32, wh + 32, wl + 32);
    }
    __syncthreads();   // all warps done reading A1/W before A2 overlay writes

    // ---- layer-1 epilogue: bias+relu+split -> A2h/A2l ----
    {
        #pragma unroll
        for (int nt = 0; nt < 8; nt++) {
            int col0 = nq * 64 + nt * 8 + (lane & 3) * 2;
            float b0 = bias1s[col0], b1v = bias1s[col0 + 1];
            #pragma unroll
            for (int mt = 0; mt < 4; mt++) {
                float4 c = acc[mt][nt];
                int row0 = mh * 64 + mt * 16 + (lane >> 2);
                float y00 = fmaxf(c.x + b0, 0.f), y01 = fmaxf(c.y + b1v, 0.f);
                float y10 = fmaxf(c.z + b0, 0.f), y11 = fmaxf(c.w + b1v, 0.f);
                unsigned short h0, l0, h1, l1;
                bsplit(y00, h0, l0); bsplit(y01, h1, l1);
                *(uint32_t*)(smem + SM_A2H + row0 * A2ROWB + col0 * 2) = h0 | ((uint32_t)h1 << 16);
                *(uint32_t*)(smem + SM_A2L + row0 * A2ROWB + col0 * 2) = l0 | ((uint32_t)l1 << 16);
                bsplit(y10, h0, l0); bsplit(y11, h1, l1);
                *(uint32_t*)(smem + SM_A2H + (row0 + 8) * A2ROWB + col0 * 2) = h0 | ((uint32_t)h1 << 16);
                *(uint32_t*)(smem + SM_A2L + (row0 + 8) * A2ROWB + col0 * 2) = l0 | ((uint32_t)l1 << 16);
            }
        }
    }
    #pragma unroll
    for (int mt = 0; mt < 4; mt++)
        #pragma unroll
        for (int nt = 0; nt < 8; nt++) acc[mt][nt] = make_float4(0.f, 0.f, 0.f, 0.f);
    __syncthreads();

    // ================= layer 2 =================
    issue2(0);
    for (int t = 0; t < CH2; t++) {
        int buf = t & 1;
        CP_WAIT0();
        __syncthreads();
        if (t + 1 < CH2) issue2(t + 1);
        uint32_t ah = sb + SM_A2H + a2_off + (uint32_t)(t * 64);
        uint32_t al = sb + SM_A2L + a2_off + (uint32_t)(t * 64);
        uint32_t wh = sb + SM_W + (uint32_t)((buf * 2    ) * 20480) + w_off;
        uint32_t wl = sb + SM_W + (uint32_t)((buf * 2 + 1) * 20480) + w_off;
        gemm_kstep<A2ROWB>(acc, ah,      al,      wh,      wl);
        gemm_kstep<A2ROWB>(acc, ah + 32, al + 32, wh + 32, wl + 32);
    }

    // ---- layer-2 epilogue: maxpool over 32 samples + bias + relu ----
    #pragma unroll
    for (int nt = 0; nt < 8; nt++) {
        float4 c0 = acc[0][nt], c1 = acc[1][nt], c2 = acc[2][nt], c3 = acc[3][nt];
        float p0a = fmaxf(fmaxf(c0.x, c0.z), fmaxf(c1.x, c1.z));   // point mh*2,   col0
        float p0b = fmaxf(fmaxf(c0.y, c0.w), fmaxf(c1.y, c1.w));   //               col0+1
        float p1a = fmaxf(fmaxf(c2.x, c2.z), fmaxf(c3.x, c3.z));   // point mh*2+1, col0
        float p1b = fmaxf(fmaxf(c2.y, c2.w), fmaxf(c3.y, c3.w));
        #pragma unroll
        for (int off = 4; off < 32; off <<= 1) {
            p0a = fmaxf(p0a, __shfl_xor_sync(0xffffffffu, p0a, off));
            p0b = fmaxf(p0b, __shfl_xor_sync(0xffffffffu, p0b, off));
            p1a = fmaxf(p1a, __shfl_xor_sync(0xffffffffu, p1a, off));
            p1b = fmaxf(p1b, __shfl_xor_sync(0xffffffffu, p1b, off));
        }
        if (lane < 4) {
            int col0 = nq * 64 + nt * 8 + lane * 2;
            int n0 = nbase + mh * 2;
            float bA = bias2s[col0], bB = bias2s[col0 + 1];
            out[((size_t)bb * 256 + col0)     * 1024 + n0]     = fmaxf(p0a + bA, 0.f);
            out[((size_t)bb * 256 + col0 + 1) * 1024 + n0]     = fmaxf(p0b + bB, 0.f);
            out[((size_t)bb * 256 + col0)     * 1024 + n0 + 1] = fmaxf(p1a + bA, 0.f);
            out[((size_t)bb * 256 + col0 + 1) * 1024 + n0 + 1] = fmaxf(p1b + bB, 0.f);
        }
    }
}

// ---------------------------------------------------------------------------
extern "C" void kernel_launch(void* const* d_in, const int* in_sizes, int n_in,
                              void* d_out, int out_size)
{
    const float* xyz  = (const float*)d_in[0];
    const float* feat = (const float*)d_in[1];
    const float* rot  = (const float*)d_in[2];
    const float* w1   = (const float*)d_in[3];
    const float* g1   = (const float*)d_in[4];
    const float* b1   = (const float*)d_in[5];
    const float* m1   = (const float*)d_in[6];
    const float* v1   = (const float*)d_in[7];
    const float* w2   = (const float*)d_in[8];
    const float* g2   = (const float*)d_in[9];
    const float* b2   = (const float*)d_in[10];
    const float* m2   = (const float*)d_in[11];
    const float* v2   = (const float*)d_in[12];
    float* out = (float*)d_out;

    cudaFuncSetAttribute(tc_mlp, cudaFuncAttributeMaxDynamicSharedMemorySize, SMEM_TOTAL);

    int prep_total = (CH1 + CH2) * 256 * 40;     // 256000
    prep_w<<<(prep_total + 255) / 256, 256>>>(w1, g1, b1, m1, v1,
                                              w2, g2, b2, m2, v2);
    transpose_feat<<<dim3(Nc / 32, CIN / 32, Bc), dim3(32, 8)>>>(feat);
    cylinder_query<<<(Bc * Nc) / 4, 128>>>(xyz, rot);
    tc_mlp<<<Bc * Nc / 4, 256, SMEM_TOTAL>>>(out);
}

// round 5
// speedup vs baseline: 4.0698x; 1.3624x over previous
#include <cuda_runtime.h>
#include <cuda_fp16.h>
#include <cstdint>

// ---------------------------------------------------------------------------
// CloudCrop via mma.sync fp16 2-product split (A = Ah+Al fp16, W = fp16 rn).
// Products Ah*W + Al*W are exact (11+11 <= 24 bits); only W rounding (~2^-12)
// survives -> norm rel_err ~3e-4 << 1e-3.
// B=4, N=1024, NS=32, 512->256->256, maxpool over 32 samples.
// ---------------------------------------------------------------------------

#define Bc 4
#define Nc 1024
#define NS 32
#define CIN 512
#define C0 515
#define RADIUSf 0.05f
#define HMINf (-0.02f)
#define HMAXf 0.04f

#define KC 32                 // K per chunk
#define KROWB 80              // padded A/W tile row bytes (40 fp16)
#define CH1 17                // layer-1 chunks (K=544; cols 544..575 all zero)
#define CH2 8                 // layer-2 chunks (K=256)
#define A2ROWB 528            // flat y1 row bytes (256 fp16 + 8 pad)

// smem offsets (dynamic)
#define SM_A2H   0
#define SM_A2L   67584
#define SM_A1    0            // 4 x 10240 (buf x {h,l}), overlays A2H
#define SM_W     135168       // 2 x 20480 (buf), single-precision W
#define SM_B1    176128
#define SM_B2    177152
#define SM_LIDX  178176
#define SMEM_TOTAL 178688

// __device__ scratch (allocation-free), 16B-aligned
__device__ __align__(16) unsigned short d_fh[Bc * Nc * CIN];   // feat hi fp16 [b][n][c]
__device__ __align__(16) unsigned short d_fl[Bc * Nc * CIN];   // feat lo fp16
__device__ __align__(16) int            d_idx[Bc * Nc * NS];
__device__ __align__(16) float          d_rel[Bc * Nc * NS * 3];
__device__ __align__(16) unsigned short d_w1[CH1 * 256 * 40];  // [t][o][40] fp16
__device__ __align__(16) unsigned short d_w2[CH2 * 256 * 40];
__device__ __align__(16) float          d_bias1[256];
__device__ __align__(16) float          d_bias2[256];

__device__ __forceinline__ void hsplit(float v, unsigned short& h, unsigned short& l) {
    __half hb = __float2half_rn(v);
    h = __half_as_ushort(hb);
    l = __half_as_ushort(__float2half_rn(v - __half2float(hb)));
}
__device__ __forceinline__ uint32_t s2u(const void* p) {
    uint32_t a;
    asm("{ .reg .u64 t; cvta.to.shared.u64 t, %1; cvt.u32.u64 %0, t; }" : "=r"(a) : "l"(p));
    return a;
}
__device__ __forceinline__ void cpa16(uint32_t dst, const void* src) {
    asm volatile("cp.async.cg.shared.global [%0], [%1], 16;" :: "r"(dst), "l"(src));
}
#define CP_COMMIT()  asm volatile("cp.async.commit_group;" ::: "memory")
#define CP_WAIT0()   asm volatile("cp.async.wait_group 0;" ::: "memory")

__device__ __forceinline__ void ldsm4(uint32_t& r0, uint32_t& r1, uint32_t& r2, uint32_t& r3,
                                      uint32_t addr) {
    asm volatile("ldmatrix.sync.aligned.m8n8.x4.shared.b16 {%0,%1,%2,%3}, [%4];"
                 : "=r"(r0), "=r"(r1), "=r"(r2), "=r"(r3) : "r"(addr));
}
#define MMA(d, A, b0r, b1r) \
    asm volatile("mma.sync.aligned.m16n8k16.row.col.f32.f16.f16.f32 " \
                 "{%0,%1,%2,%3},{%4,%5,%6,%7},{%8,%9},{%0,%1,%2,%3};" \
                 : "+f"((d).x), "+f"((d).y), "+f"((d).z), "+f"((d).w) \
                 : "r"((A)[0]), "r"((A)[1]), "r"((A)[2]), "r"((A)[3]), \
                   "r"(b0r), "r"(b1r))

// One k16 step: acc += Ah*W + Al*W  (64 HMMA)
template<int AROW>
__device__ __forceinline__ void gemm_kstep(float4 (&acc)[4][8],
    uint32_t ah, uint32_t al, uint32_t wb)
{
    uint32_t Ah[4][4], Al[4][4], Bf[4][4];
    #pragma unroll
    for (int mt = 0; mt < 4; mt++) {
        ldsm4(Ah[mt][0], Ah[mt][1], Ah[mt][2], Ah[mt][3], ah + mt * 16 * AROW);
        ldsm4(Al[mt][0], Al[mt][1], Al[mt][2], Al[mt][3], al + mt * 16 * AROW);
    }
    #pragma unroll
    for (int p = 0; p < 4; p++)
        ldsm4(Bf[p][0], Bf[p][1], Bf[p][2], Bf[p][3], wb + p * 16 * KROWB);
    #pragma unroll
    for (int mt = 0; mt < 4; mt++) {
        #pragma unroll
        for (int p = 0; p < 4; p++) {
            MMA(acc[mt][2*p],   Ah[mt], Bf[p][0], Bf[p][1]);
            MMA(acc[mt][2*p],   Al[mt], Bf[p][0], Bf[p][1]);
            MMA(acc[mt][2*p+1], Ah[mt], Bf[p][2], Bf[p][3]);
            MMA(acc[mt][2*p+1], Al[mt], Bf[p][2], Bf[p][3]);
        }
    }
}

// ---------------------------------------------------------------------------
// Prep: fold BN into weights -> fp16 rn, padded chunked layout [t][o][40].
// Column map: c<512 -> w1 col c+3 (features); 512..514 -> w1 cols 0..2 (rel).
// ---------------------------------------------------------------------------
__global__ void prep_w(const float* __restrict__ w1,
                       const float* __restrict__ g1, const float* __restrict__ b1,
                       const float* __restrict__ m1, const float* __restrict__ v1,
                       const float* __restrict__ w2,
                       const float* __restrict__ g2, const float* __restrict__ b2,
                       const float* __restrict__ m2, const float* __restrict__ v2)
{
    int i = blockIdx.x * blockDim.x + threadIdx.x;
    const int W1E = CH1 * 256 * 40;
    const int W2E = CH2 * 256 * 40;
    if (i < W1E) {
        int t = i / 10240, rem = i % 10240, o = rem / 40, k = rem % 40;
        int c = t * KC + k;
        float val = 0.f;
        if (k < KC) {
            float s = g1[o] * rsqrtf(v1[o] + 1e-5f);
            if (c < 512)      val = w1[o * C0 + c + 3] * s;
            else if (c < 515) val = w1[o * C0 + (c - 512)] * s;
        }
        d_w1[i] = __half_as_ushort(__float2half_rn(val));
    }
    int j = i - W1E;
    if (j >= 0 && j < W2E) {
        int t = j / 10240, rem = j % 10240, o = rem / 40, k = rem % 40;
        float val = 0.f;
        if (k < KC) {
            float s = g2[o] * rsqrtf(v2[o] + 1e-5f);
            val = w2[o * 256 + t * KC + k] * s;
        }
        d_w2[j] = __half_as_ushort(__float2half_rn(val));
    }
    if (i < 256) {
        float s1 = g1[i] * rsqrtf(v1[i] + 1e-5f);
        d_bias1[i] = b1[i] - m1[i] * s1;
        float s2 = g2[i] * rsqrtf(v2[i] + 1e-5f);
        d_bias2[i] = b2[i] - m2[i] * s2;
    }
}

// Transpose [B,512,N] -> point-major hi/lo fp16 [B,N,512]
__global__ void transpose_feat(const float* __restrict__ f)
{
    __shared__ float tile[32][33];
    int b  = blockIdx.z;
    int c0 = blockIdx.y * 32;
    int n0 = blockIdx.x * 32;
    int tx = threadIdx.x, ty = threadIdx.y;
    const float* src = f + (size_t)b * CIN * Nc;
    #pragma unroll
    for (int k = 0; k < 32; k += 8)
        tile[ty + k][tx] = src[(c0 + ty + k) * Nc + n0 + tx];
    __syncthreads();
    size_t base = (size_t)b * Nc * CIN;
    #pragma unroll
    for (int k = 0; k < 32; k += 8) {
        float v = tile[tx][ty + k];
        unsigned short h, l; hsplit(v, h, l);
        size_t o = base + (size_t)(n0 + ty + k) * CIN + c0 + tx;
        d_fh[o] = h; d_fl[o] = l;
    }
}

__global__ void cylinder_query(const float* __restrict__ xyz,
                               const float* __restrict__ rot)
{
    __shared__ int sidx[4][NS];
    int w    = threadIdx.x >> 5;
    int lane = threadIdx.x & 31;
    int p = blockIdx.x * 4 + w;
    int b = p >> 10, n = p & 1023;

    const float* X = xyz + (size_t)b * Nc * 3;
    float cx = X[n * 3 + 0], cy = X[n * 3 + 1], cz = X[n * 3 + 2];
    const float* R = rot + (size_t)p * 9;
    float r00 = R[0], r01 = R[1], r02 = R[2];
    float r10 = R[3], r11 = R[4], r12 = R[5];
    float r20 = R[6], r21 = R[7], r22 = R[8];
    const float R2 = RADIUSf * RADIUSf;

    int cnt = 0;
    for (int m0 = 0; m0 < Nc; m0 += 32) {
        int m = m0 + lane;
        float dx = X[m * 3 + 0] - cx;
        float dy = X[m * 3 + 1] - cy;
        float dz = X[m * 3 + 2] - cz;
        float xr = r00 * dx + r01 * dy + r02 * dz;
        float yr = r10 * dx + r11 * dy + r12 * dz;
        float zr = r20 * dx + r21 * dy + r22 * dz;
        bool mk = (yr * yr + zr * zr < R2) && (xr > HMINf) && (xr < HMAXf);
        unsigned bal = __ballot_sync(0xffffffffu, mk);
        int pre = __popc(bal & ((1u << lane) - 1u));
        int slot = cnt + pre;
        if (mk && slot < NS) sidx[w][slot] = m;
        cnt += __popc(bal);
        if (cnt >= NS) break;
    }
    __syncwarp();
    int c32 = cnt < NS ? cnt : NS;
    int pad = (cnt > 0) ? sidx[w][0] : 0;
    int j = (lane < c32) ? sidx[w][lane] : pad;

    d_idx[p * NS + lane] = j;
    float dx = X[j * 3 + 0] - cx;
    float dy = X[j * 3 + 1] - cy;
    float dz = X[j * 3 + 2] - cz;
    float inv = 1.0f / RADIUSf;
    d_rel[(p * NS + lane) * 3 + 0] = (dx * r00 + dy * r10 + dz * r20) * inv;
    d_rel[(p * NS + lane) * 3 + 1] = (dx * r01 + dy * r11 + dz * r21) * inv;
    d_rel[(p * NS + lane) * 3 + 2] = (dx * r02 + dy * r12 + dz * r22) * inv;
}

// ---------------------------------------------------------------------------
// Main: one CTA = 4 points (M=128), N=256. 8 warps, 64x64 warp tiles.
// cp.async 2-deep pipeline; layer1 -> regs -> relu/split -> smem A2 -> layer2.
// ---------------------------------------------------------------------------
__global__ void __launch_bounds__(256, 1)
tc_mlp(float* __restrict__ out)
{
    extern __shared__ char smem[];
    uint32_t sb = s2u(smem);
    int tid  = threadIdx.x;
    int lane = tid & 31;
    int w    = tid >> 5;
    int mh   = w >> 2;            // m-half (0/1): rows mh*64..
    int nq   = w & 3;             // n-quarter: cols nq*64..
    int blk  = blockIdx.x;
    int bb   = blk >> 8;
    int nbase = (blk & 255) * 4;

    float* bias1s = (float*)(smem + SM_B1);
    float* bias2s = (float*)(smem + SM_B2);
    int*   lidx   = (int*)(smem + SM_LIDX);

    if (tid < 128) lidx[tid] = d_idx[blk * 128 + tid];
    bias1s[tid] = d_bias1[tid];
    bias2s[tid] = d_bias2[tid];
    __syncthreads();

    // batch-local feature bases
    const char* fbh = (const char*)d_fh + (size_t)bb * (Nc * CIN * 2);
    const char* fbl = (const char*)d_fl + (size_t)bb * (Nc * CIN * 2);

    // lane-dependent fragment offsets
    uint32_t a1_off = (uint32_t)((mh * 64 + (lane & 15)) * KROWB + (lane >> 4) * 16);
    uint32_t a2_off = (uint32_t)((mh * 64 + (lane & 15)) * A2ROWB + (lane >> 4) * 16);
    uint32_t w_off  = (uint32_t)((nq * 64 + (lane & 7) + ((lane >> 4) << 3)) * KROWB
                                 + ((lane >> 3) & 1) * 16);

    // ---- prefetch helpers ----
    auto issue1 = [&](int t) {
        int buf = t & 1;
        if (t < 16) {
            #pragma unroll
            for (int it = 0; it < 4; it++) {
                int e = tid + it * 256;            // 0..1023
                int hl = e >> 9, r = (e >> 2) & 127, q = e & 3;
                uint32_t dst = sb + SM_A1 + (uint32_t)((buf * 2 + hl) * 10240 + r * KROWB + q * 16);
                const char* srcb = (hl ? fbl : fbh)
                                 + (size_t)lidx[r] * 1024 + t * 64 + q * 16;
                cpa16(dst, srcb);
            }
        } else {
            // rel chunk: zero both tiles, then 3 real columns
            uint32_t* za = (uint32_t*)(smem + SM_A1 + (buf * 2) * 10240);
            #pragma unroll
            for (int it = 0; it < 20; it++) za[tid + it * 256] = 0;
            if (tid < 128) {
                int r = tid;
                #pragma unroll
                for (int k = 0; k < 3; k++) {
                    float v = d_rel[(blk * 128 + r) * 3 + k];
                    unsigned short h, l; hsplit(v, h, l);
                    *(unsigned short*)(smem + SM_A1 + (buf * 2) * 10240     + r * KROWB + k * 2) = h;
                    *(unsigned short*)(smem + SM_A1 + (buf * 2 + 1) * 10240 + r * KROWB + k * 2) = l;
                }
            }
        }
        #pragma unroll
        for (int it = 0; it < 5; it++) {
            int e = tid + it * 256;                // 0..1279
            uint32_t dst = sb + SM_W + (uint32_t)((t & 1) * 20480 + e * 16);
            const char* srcb = (const char*)d_w1 + (size_t)t * 20480 + e * 16;
            cpa16(dst, srcb);
        }
        CP_COMMIT();
    };
    auto issue2 = [&](int t) {
        #pragma unroll
        for (int it = 0; it < 5; it++) {
            int e = tid + it * 256;
            uint32_t dst = sb + SM_W + (uint32_t)((t & 1) * 20480 + e * 16);
            const char* srcb = (const char*)d_w2 + (size_t)t * 20480 + e * 16;
            cpa16(dst, srcb);
        }
        CP_COMMIT();
    };

    float4 acc[4][8];
    #pragma unroll
    for (int mt = 0; mt < 4; mt++)
        #pragma unroll
        for (int nt = 0; nt < 8; nt++) acc[mt][nt] = make_float4(0.f, 0.f, 0.f, 0.f);

    // ================= layer 1 =================
    issue1(0);
    for (int t = 0; t < CH1; t++) {
        int buf = t & 1;
        CP_WAIT0();
        __syncthreads();
        if (t + 1 < CH1) issue1(t + 1);
        uint32_t ah = sb + SM_A1 + (uint32_t)((buf * 2    ) * 10240) + a1_off;
        uint32_t al = sb + SM_A1 + (uint32_t)((buf * 2 + 1) * 10240) + a1_off;
        uint32_t wb = sb + SM_W  + (uint32_t)(buf * 20480) + w_off;
        gemm_kstep<KROWB>(acc, ah,      al,      wb);
        gemm_kstep<KROWB>(acc, ah + 32, al + 32, wb + 32);
    }
    __syncthreads();   // all warps done reading A1/W before A2 overlay writes

    // ---- layer-1 epilogue: bias+relu+split -> A2h/A2l ----
    {
        #pragma unroll
        for (int nt = 0; nt < 8; nt++) {
            int col0 = nq * 64 + nt * 8 + (lane & 3) * 2;
            float b0 = bias1s[col0], b1v = bias1s[col0 + 1];
            #pragma unroll
            for (int mt = 0; mt < 4; mt++) {
                float4 c = acc[mt][nt];
                int row0 = mh * 64 + mt * 16 + (lane >> 2);
                float y00 = fmaxf(c.x + b0, 0.f), y01 = fmaxf(c.y + b1v, 0.f);
                float y10 = fmaxf(c.z + b0, 0.f), y11 = fmaxf(c.w + b1v, 0.f);
                unsigned short h0, l0, h1, l1;
                hsplit(y00, h0, l0); hsplit(y01, h1, l1);
                *(uint32_t*)(smem + SM_A2H + row0 * A2ROWB + col0 * 2) = h0 | ((uint32_t)h1 << 16);
                *(uint32_t*)(smem + SM_A2L + row0 * A2ROWB + col0 * 2) = l0 | ((uint32_t)l1 << 16);
                hsplit(y10, h0, l0); hsplit(y11, h1, l1);
                *(uint32_t*)(smem + SM_A2H + (row0 + 8) * A2ROWB + col0 * 2) = h0 | ((uint32_t)h1 << 16);
                *(uint32_t*)(smem + SM_A2L + (row0 + 8) * A2ROWB + col0 * 2) = l0 | ((uint32_t)l1 << 16);
            }
        }
    }
    #pragma unroll
    for (int mt = 0; mt < 4; mt++)
        #pragma unroll
        for (int nt = 0; nt < 8; nt++) acc[mt][nt] = make_float4(0.f, 0.f, 0.f, 0.f);
    __syncthreads();

    // ================= layer 2 =================
    issue2(0);
    for (int t = 0; t < CH2; t++) {
        int buf = t & 1;
        CP_WAIT0();
        __syncthreads();
        if (t + 1 < CH2) issue2(t + 1);
        uint32_t ah = sb + SM_A2H + a2_off + (uint32_t)(t * 64);
        uint32_t al = sb + SM_A2L + a2_off + (uint32_t)(t * 64);
        uint32_t wb = sb + SM_W + (uint32_t)(buf * 20480) + w_off;
        gemm_kstep<A2ROWB>(acc, ah,      al,      wb);
        gemm_kstep<A2ROWB>(acc, ah + 32, al + 32, wb + 32);
    }

    // ---- layer-2 epilogue: maxpool over 32 samples + bias + relu ----
    #pragma unroll
    for (int nt = 0; nt < 8; nt++) {
        float4 c0 = acc[0][nt], c1 = acc[1][nt], c2 = acc[2][nt], c3 = acc[3][nt];
        float p0a = fmaxf(fmaxf(c0.x, c0.z), fmaxf(c1.x, c1.z));   // point mh*2,   col0
        float p0b = fmaxf(fmaxf(c0.y, c0.w), fmaxf(c1.y, c1.w));   //               col0+1
        float p1a = fmaxf(fmaxf(c2.x, c2.z), fmaxf(c3.x, c3.z));   // point mh*2+1, col0
        float p1b = fmaxf(fmaxf(c2.y, c2.w), fmaxf(c3.y, c3.w));
        #pragma unroll
        for (int off = 4; off < 32; off <<= 1) {
            p0a = fmaxf(p0a, __shfl_xor_sync(0xffffffffu, p0a, off));
            p0b = fmaxf(p0b, __shfl_xor_sync(0xffffffffu, p0b, off));
            p1a = fmaxf(p1a, __shfl_xor_sync(0xffffffffu, p1a, off));
            p1b = fmaxf(p1b, __shfl_xor_sync(0xffffffffu, p1b, off));
        }
        if (lane < 4) {
            int col0 = nq * 64 + nt * 8 + lane * 2;
            int n0 = nbase + mh * 2;
            float bA = bias2s[col0], bB = bias2s[col0 + 1];
            out[((size_t)bb * 256 + col0)     * 1024 + n0]     = fmaxf(p0a + bA, 0.f);
            out[((size_t)bb * 256 + col0 + 1) * 1024 + n0]     = fmaxf(p0b + bB, 0.f);
            out[((size_t)bb * 256 + col0)     * 1024 + n0 + 1] = fmaxf(p1a + bA, 0.f);
            out[((size_t)bb * 256 + col0 + 1) * 1024 + n0 + 1] = fmaxf(p1b + bB, 0.f);
        }
    }
}

// ---------------------------------------------------------------------------
extern "C" void kernel_launch(void* const* d_in, const int* in_sizes, int n_in,
                              void* d_out, int out_size)
{
    const float* xyz  = (const float*)d_in[0];
    const float* feat = (const float*)d_in[1];
    const float* rot  = (const float*)d_in[2];
    const float* w1   = (const float*)d_in[3];
    const float* g1   = (const float*)d_in[4];
    const float* b1   = (const float*)d_in[5];
    const float* m1   = (const float*)d_in[6];
    const float* v1   = (const float*)d_in[7];
    const float* w2   = (const float*)d_in[8];
    const float* g2   = (const float*)d_in[9];
    const float* b2   = (const float*)d_in[10];
    const float* m2   = (const float*)d_in[11];
    const float* v2   = (const float*)d_in[12];
    float* out = (float*)d_out;

    cudaFuncSetAttribute(tc_mlp, cudaFuncAttributeMaxDynamicSharedMemorySize, SMEM_TOTAL);

    int prep_total = (CH1 + CH2) * 256 * 40;     // 256000
    prep_w<<<(prep_total + 255) / 256, 256>>>(w1, g1, b1, m1, v1,
                                              w2, g2, b2, m2, v2);
    transpose_feat<<<dim3(Nc / 32, CIN / 32, Bc), dim3(32, 8)>>>(feat);
    cylinder_query<<<(Bc * Nc) / 4, 128>>>(xyz, rot);
    tc_mlp<<<Bc * Nc / 4, 256, SMEM_TOTAL>>>(out);
}

// round 6
// speedup vs baseline: 6.2929x; 1.5462x over previous
#include <cuda_runtime.h>
#include <cuda_fp16.h>
#include <cstdint>

// ---------------------------------------------------------------------------
// CloudCrop via mma.sync fp16 single-product (A fp16 rn, W fp16 rn, fp32 acc).
// Error: A+W rounding ~2^-12 each -> norm rel_err ~2.5e-4 < 1e-3.
// K-chunks of 64 (half the barrier rounds of R5).
// B=4, N=1024, NS=32, 512->256->256, maxpool over 32 samples.
// ---------------------------------------------------------------------------

#define Bc 4
#define Nc 1024
#define NS 32
#define CIN 512
#define C0 515
#define RADIUSf 0.05f
#define HMINf (-0.02f)
#define HMAXf 0.04f

#define KROWB 144             // A/W tile row bytes (64 fp16 + 16B pad)
#define CH1 9                 // layer-1 chunks of K=64 (K=576; chunk 8 = rel+pad)
#define CH2 4                 // layer-2 chunks (K=256)
#define A2ROWB 528            // y1 row bytes (256 fp16 + 16B pad)
#define A1BUF 18432           // 128 rows * 144B
#define WBUF  36864           // 256 rows * 144B

// smem offsets (dynamic)
#define SM_A2    0            // 128 x 528 = 67584
#define SM_A1    0            // 2 x 18432 (overlays A2; dead until L1 epilogue)
#define SM_W     67584        // 2 x 36864
#define SM_B1    141312
#define SM_B2    142336
#define SM_LIDX  143360
#define SMEM_TOTAL 143872

// __device__ scratch (allocation-free), 16B-aligned
__device__ __align__(16) unsigned short d_fh[Bc * Nc * CIN];   // feat fp16 [b][n][c]
__device__ __align__(16) int            d_idx[Bc * Nc * NS];
__device__ __align__(16) float          d_rel[Bc * Nc * NS * 3];
__device__ __align__(16) unsigned short d_w1[CH1 * 256 * 64];  // [t][o][64] fp16
__device__ __align__(16) unsigned short d_w2[CH2 * 256 * 64];
__device__ __align__(16) float          d_bias1[256];
__device__ __align__(16) float          d_bias2[256];

__device__ __forceinline__ uint32_t s2u(const void* p) {
    uint32_t a;
    asm("{ .reg .u64 t; cvta.to.shared.u64 t, %1; cvt.u32.u64 %0, t; }" : "=r"(a) : "l"(p));
    return a;
}
__device__ __forceinline__ void cpa16(uint32_t dst, const void* src) {
    asm volatile("cp.async.cg.shared.global [%0], [%1], 16;" :: "r"(dst), "l"(src));
}
#define CP_COMMIT()  asm volatile("cp.async.commit_group;" ::: "memory")
#define CP_WAIT0()   asm volatile("cp.async.wait_group 0;" ::: "memory")

__device__ __forceinline__ void ldsm4(uint32_t& r0, uint32_t& r1, uint32_t& r2, uint32_t& r3,
                                      uint32_t addr) {
    asm volatile("ldmatrix.sync.aligned.m8n8.x4.shared.b16 {%0,%1,%2,%3}, [%4];"
                 : "=r"(r0), "=r"(r1), "=r"(r2), "=r"(r3) : "r"(addr));
}
#define MMA(d, A, b0r, b1r) \
    asm volatile("mma.sync.aligned.m16n8k16.row.col.f32.f16.f16.f32 " \
                 "{%0,%1,%2,%3},{%4,%5,%6,%7},{%8,%9},{%0,%1,%2,%3};" \
                 : "+f"((d).x), "+f"((d).y), "+f"((d).z), "+f"((d).w) \
                 : "r"((A)[0]), "r"((A)[1]), "r"((A)[2]), "r"((A)[3]), \
                   "r"(b0r), "r"(b1r))

// One k16 step: acc += A*W  (32 HMMA)
template<int AROW>
__device__ __forceinline__ void gemm_kstep(float4 (&acc)[4][8], uint32_t a, uint32_t wb)
{
    uint32_t Ax[4][4], Bf[4][4];
    #pragma unroll
    for (int mt = 0; mt < 4; mt++)
        ldsm4(Ax[mt][0], Ax[mt][1], Ax[mt][2], Ax[mt][3], a + mt * 16 * AROW);
    #pragma unroll
    for (int p = 0; p < 4; p++)
        ldsm4(Bf[p][0], Bf[p][1], Bf[p][2], Bf[p][3], wb + p * 16 * KROWB);
    #pragma unroll
    for (int mt = 0; mt < 4; mt++) {
        #pragma unroll
        for (int p = 0; p < 4; p++) {
            MMA(acc[mt][2*p],   Ax[mt], Bf[p][0], Bf[p][1]);
            MMA(acc[mt][2*p+1], Ax[mt], Bf[p][2], Bf[p][3]);
        }
    }
}

// ---------------------------------------------------------------------------
// Prep: fold BN into weights -> fp16 rn, chunked layout [t][o][64] unpadded.
// Column map: c<512 -> w1 col c+3 (features); 512..514 -> w1 cols 0..2 (rel).
// ---------------------------------------------------------------------------
__global__ void prep_w(const float* __restrict__ w1,
                       const float* __restrict__ g1, const float* __restrict__ b1,
                       const float* __restrict__ m1, const float* __restrict__ v1,
                       const float* __restrict__ w2,
                       const float* __restrict__ g2, const float* __restrict__ b2,
                       const float* __restrict__ m2, const float* __restrict__ v2)
{
    int i = blockIdx.x * blockDim.x + threadIdx.x;
    const int W1E = CH1 * 256 * 64;   // 147456
    const int W2E = CH2 * 256 * 64;   // 65536
    if (i < W1E) {
        int t = i >> 14, rem = i & 16383, o = rem >> 6, k = rem & 63;
        int c = t * 64 + k;
        float s = g1[o] * rsqrtf(v1[o] + 1e-5f);
        float val = 0.f;
        if (c < 512)      val = w1[o * C0 + c + 3] * s;
        else if (c < 515) val = w1[o * C0 + (c - 512)] * s;
        d_w1[i] = __half_as_ushort(__float2half_rn(val));
    }
    int j = i - W1E;
    if (j >= 0 && j < W2E) {
        int t = j >> 14, rem = j & 16383, o = rem >> 6, k = rem & 63;
        float s = g2[o] * rsqrtf(v2[o] + 1e-5f);
        d_w2[j] = __half_as_ushort(__float2half_rn(w2[o * 256 + t * 64 + k] * s));
    }
    if (i < 256) {
        float s1 = g1[i] * rsqrtf(v1[i] + 1e-5f);
        d_bias1[i] = b1[i] - m1[i] * s1;
        float s2 = g2[i] * rsqrtf(v2[i] + 1e-5f);
        d_bias2[i] = b2[i] - m2[i] * s2;
    }
}

// Transpose [B,512,N] -> point-major fp16 [B,N,512]
__global__ void transpose_feat(const float* __restrict__ f)
{
    __shared__ float tile[32][33];
    int b  = blockIdx.z;
    int c0 = blockIdx.y * 32;
    int n0 = blockIdx.x * 32;
    int tx = threadIdx.x, ty = threadIdx.y;
    const float* src = f + (size_t)b * CIN * Nc;
    #pragma unroll
    for (int k = 0; k < 32; k += 8)
        tile[ty + k][tx] = src[(c0 + ty + k) * Nc + n0 + tx];
    __syncthreads();
    size_t base = (size_t)b * Nc * CIN;
    #pragma unroll
    for (int k = 0; k < 32; k += 8) {
        float v = tile[tx][ty + k];
        d_fh[base + (size_t)(n0 + ty + k) * CIN + c0 + tx] =
            __half_as_ushort(__float2half_rn(v));
    }
}

__global__ void cylinder_query(const float* __restrict__ xyz,
                               const float* __restrict__ rot)
{
    __shared__ int sidx[4][NS];
    int w    = threadIdx.x >> 5;
    int lane = threadIdx.x & 31;
    int p = blockIdx.x * 4 + w;
    int b = p >> 10, n = p & 1023;

    const float* X = xyz + (size_t)b * Nc * 3;
    float cx = X[n * 3 + 0], cy = X[n * 3 + 1], cz = X[n * 3 + 2];
    const float* R = rot + (size_t)p * 9;
    float r00 = R[0], r01 = R[1], r02 = R[2];
    float r10 = R[3], r11 = R[4], r12 = R[5];
    float r20 = R[6], r21 = R[7], r22 = R[8];
    const float R2 = RADIUSf * RADIUSf;

    int cnt = 0;
    for (int m0 = 0; m0 < Nc; m0 += 32) {
        int m = m0 + lane;
        float dx = X[m * 3 + 0] - cx;
        float dy = X[m * 3 + 1] - cy;
        float dz = X[m * 3 + 2] - cz;
        float xr = r00 * dx + r01 * dy + r02 * dz;
        float yr = r10 * dx + r11 * dy + r12 * dz;
        float zr = r20 * dx + r21 * dy + r22 * dz;
        bool mk = (yr * yr + zr * zr < R2) && (xr > HMINf) && (xr < HMAXf);
        unsigned bal = __ballot_sync(0xffffffffu, mk);
        int pre = __popc(bal & ((1u << lane) - 1u));
        int slot = cnt + pre;
        if (mk && slot < NS) sidx[w][slot] = m;
        cnt += __popc(bal);
        if (cnt >= NS) break;
    }
    __syncwarp();
    int c32 = cnt < NS ? cnt : NS;
    int pad = (cnt > 0) ? sidx[w][0] : 0;
    int j = (lane < c32) ? sidx[w][lane] : pad;

    d_idx[p * NS + lane] = j;
    float dx = X[j * 3 + 0] - cx;
    float dy = X[j * 3 + 1] - cy;
    float dz = X[j * 3 + 2] - cz;
    float inv = 1.0f / RADIUSf;
    d_rel[(p * NS + lane) * 3 + 0] = (dx * r00 + dy * r10 + dz * r20) * inv;
    d_rel[(p * NS + lane) * 3 + 1] = (dx * r01 + dy * r11 + dz * r21) * inv;
    d_rel[(p * NS + lane) * 3 + 2] = (dx * r02 + dy * r12 + dz * r22) * inv;
}

// ---------------------------------------------------------------------------
// Main: one CTA = 4 points (M=128), N=256. 8 warps, 64x64 warp tiles.
// cp.async 2-deep pipeline, K=64 chunks; layer1 -> regs -> relu -> fp16 A2 ->
// layer2 -> maxpool.
// ---------------------------------------------------------------------------
__global__ void __launch_bounds__(256, 1)
tc_mlp(float* __restrict__ out)
{
    extern __shared__ char smem[];
    uint32_t sb = s2u(smem);
    int tid  = threadIdx.x;
    int lane = tid & 31;
    int w    = tid >> 5;
    int mh   = w >> 2;            // m-half (0/1): rows mh*64..
    int nq   = w & 3;             // n-quarter: cols nq*64..
    int blk  = blockIdx.x;
    int bb   = blk >> 8;
    int nbase = (blk & 255) * 4;

    float* bias1s = (float*)(smem + SM_B1);
    float* bias2s = (float*)(smem + SM_B2);
    int*   lidx   = (int*)(smem + SM_LIDX);

    if (tid < 128) lidx[tid] = d_idx[blk * 128 + tid];
    bias1s[tid] = d_bias1[tid];
    bias2s[tid] = d_bias2[tid];
    __syncthreads();

    const char* fbh = (const char*)d_fh + (size_t)bb * (Nc * CIN * 2);

    // lane-dependent fragment offsets
    uint32_t a1_off = (uint32_t)((mh * 64 + (lane & 15)) * KROWB + (lane >> 4) * 16);
    uint32_t a2_off = (uint32_t)((mh * 64 + (lane & 15)) * A2ROWB + (lane >> 4) * 16);
    uint32_t w_off  = (uint32_t)((nq * 64 + (lane & 7) + ((lane >> 4) << 3)) * KROWB
                                 + ((lane >> 3) & 1) * 16);

    // ---- prefetch helpers ----
    auto issue1 = [&](int t) {
        int buf = t & 1;
        if (t < 8) {
            #pragma unroll
            for (int it = 0; it < 4; it++) {
                int e = tid + it * 256;            // 0..1023
                int r = e >> 3, q = e & 7;
                uint32_t dst = sb + SM_A1 + (uint32_t)(buf * A1BUF + r * KROWB + q * 16);
                const char* srcb = fbh + (size_t)lidx[r] * 1024 + t * 128 + q * 16;
                cpa16(dst, srcb);
            }
        } else {
            // rel chunk: zero tile, then 3 real columns
            uint32_t* za = (uint32_t*)(smem + SM_A1 + buf * A1BUF);
            #pragma unroll
            for (int it = 0; it < 18; it++) za[tid + it * 256] = 0;
            if (tid < 128) {
                int r = tid;
                #pragma unroll
                for (int k = 0; k < 3; k++) {
                    float v = d_rel[(blk * 128 + r) * 3 + k];
                    *(unsigned short*)(smem + SM_A1 + buf * A1BUF + r * KROWB + k * 2) =
                        __half_as_ushort(__float2half_rn(v));
                }
            }
        }
        #pragma unroll
        for (int it = 0; it < 8; it++) {
            int e = tid + it * 256;                // 0..2047
            uint32_t dst = sb + SM_W + (uint32_t)((t & 1) * WBUF + (e >> 3) * KROWB + (e & 7) * 16);
            const char* srcb = (const char*)d_w1 + (size_t)t * 32768 + e * 16;
            cpa16(dst, srcb);
        }
        CP_COMMIT();
    };
    auto issue2 = [&](int t) {
        #pragma unroll
        for (int it = 0; it < 8; it++) {
            int e = tid + it * 256;
            uint32_t dst = sb + SM_W + (uint32_t)((t & 1) * WBUF + (e >> 3) * KROWB + (e & 7) * 16);
            const char* srcb = (const char*)d_w2 + (size_t)t * 32768 + e * 16;
            cpa16(dst, srcb);
        }
        CP_COMMIT();
    };

    float4 acc[4][8];
    #pragma unroll
    for (int mt = 0; mt < 4; mt++)
        #pragma unroll
        for (int nt = 0; nt < 8; nt++) acc[mt][nt] = make_float4(0.f, 0.f, 0.f, 0.f);

    // ================= layer 1 =================
    issue1(0);
    for (int t = 0; t < CH1; t++) {
        int buf = t & 1;
        CP_WAIT0();
        __syncthreads();
        if (t + 1 < CH1) issue1(t + 1);
        uint32_t a  = sb + SM_A1 + (uint32_t)(buf * A1BUF) + a1_off;
        uint32_t wb = sb + SM_W  + (uint32_t)(buf * WBUF)  + w_off;
        #pragma unroll
        for (int kk = 0; kk < 4; kk++)
            gemm_kstep<KROWB>(acc, a + kk * 32, wb + kk * 32);
    }
    __syncthreads();   // all warps done reading A1/W before A2 overlay writes

    // ---- layer-1 epilogue: bias+relu -> fp16 A2 ----
    {
        #pragma unroll
        for (int nt = 0; nt < 8; nt++) {
            int col0 = nq * 64 + nt * 8 + (lane & 3) * 2;
            float b0 = bias1s[col0], b1v = bias1s[col0 + 1];
            #pragma unroll
            for (int mt = 0; mt < 4; mt++) {
                float4 c = acc[mt][nt];
                int row0 = mh * 64 + mt * 16 + (lane >> 2);
                unsigned short h0 = __half_as_ushort(__float2half_rn(fmaxf(c.x + b0,  0.f)));
                unsigned short h1 = __half_as_ushort(__float2half_rn(fmaxf(c.y + b1v, 0.f)));
                *(uint32_t*)(smem + SM_A2 + row0 * A2ROWB + col0 * 2) = h0 | ((uint32_t)h1 << 16);
                h0 = __half_as_ushort(__float2half_rn(fmaxf(c.z + b0,  0.f)));
                h1 = __half_as_ushort(__float2half_rn(fmaxf(c.w + b1v, 0.f)));
                *(uint32_t*)(smem + SM_A2 + (row0 + 8) * A2ROWB + col0 * 2) = h0 | ((uint32_t)h1 << 16);
            }
        }
    }
    #pragma unroll
    for (int mt = 0; mt < 4; mt++)
        #pragma unroll
        for (int nt = 0; nt < 8; nt++) acc[mt][nt] = make_float4(0.f, 0.f, 0.f, 0.f);
    __syncthreads();

    // ================= layer 2 =================
    issue2(0);
    for (int t = 0; t < CH2; t++) {
        int buf = t & 1;
        CP_WAIT0();
        __syncthreads();
        if (t + 1 < CH2) issue2(t + 1);
        uint32_t a  = sb + SM_A2 + a2_off + (uint32_t)(t * 128);
        uint32_t wb = sb + SM_W + (uint32_t)(buf * WBUF) + w_off;
        #pragma unroll
        for (int kk = 0; kk < 4; kk++)
            gemm_kstep<A2ROWB>(acc, a + kk * 32, wb + kk * 32);
    }

    // ---- layer-2 epilogue: maxpool over 32 samples + bias + relu ----
    #pragma unroll
    for (int nt = 0; nt < 8; nt++) {
        float4 c0 = acc[0][nt], c1 = acc[1][nt], c2 = acc[2][nt], c3 = acc[3][nt];
        float p0a = fmaxf(fmaxf(c0.x, c0.z), fmaxf(c1.x, c1.z));   // point mh*2,   col0
        float p0b = fmaxf(fmaxf(c0.y, c0.w), fmaxf(c1.y, c1.w));   //               col0+1
        float p1a = fmaxf(fmaxf(c2.x, c2.z), fmaxf(c3.x, c3.z));   // point mh*2+1, col0
        float p1b = fmaxf(fmaxf(c2.y, c2.w), fmaxf(c3.y, c3.w));
        #pragma unroll
        for (int off = 4; off < 32; off <<= 1) {
            p0a = fmaxf(p0a, __shfl_xor_sync(0xffffffffu, p0a, off));
            p0b = fmaxf(p0b, __shfl_xor_sync(0xffffffffu, p0b, off));
            p1a = fmaxf(p1a, __shfl_xor_sync(0xffffffffu, p1a, off));
            p1b = fmaxf(p1b, __shfl_xor_sync(0xffffffffu, p1b, off));
        }
        if (lane < 4) {
            int col0 = nq * 64 + nt * 8 + lane * 2;
            int n0 = nbase + mh * 2;
            float bA = bias2s[col0], bB = bias2s[col0 + 1];
            out[((size_t)bb * 256 + col0)     * 1024 + n0]     = fmaxf(p0a + bA, 0.f);
            out[((size_t)bb * 256 + col0 + 1) * 1024 + n0]     = fmaxf(p0b + bB, 0.f);
            out[((size_t)bb * 256 + col0)     * 1024 + n0 + 1] = fmaxf(p1a + bA, 0.f);
            out[((size_t)bb * 256 + col0 + 1) * 1024 + n0 + 1] = fmaxf(p1b + bB, 0.f);
        }
    }
}

// ---------------------------------------------------------------------------
extern "C" void kernel_launch(void* const* d_in, const int* in_sizes, int n_in,
                              void* d_out, int out_size)
{
    const float* xyz  = (const float*)d_in[0];
    const float* feat = (const float*)d_in[1];
    const float* rot  = (const float*)d_in[2];
    const float* w1   = (const float*)d_in[3];
    const float* g1   = (const float*)d_in[4];
    const float* b1   = (const float*)d_in[5];
    const float* m1   = (const float*)d_in[6];
    const float* v1   = (const float*)d_in[7];
    const float* w2   = (const float*)d_in[8];
    const float* g2   = (const float*)d_in[9];
    const float* b2   = (const float*)d_in[10];
    const float* m2   = (const float*)d_in[11];
    const float* v2   = (const float*)d_in[12];
    float* out = (float*)d_out;

    cudaFuncSetAttribute(tc_mlp, cudaFuncAttributeMaxDynamicSharedMemorySize, SMEM_TOTAL);

    int prep_total = (CH1 + CH2) * 256 * 64;     // 212992
    prep_w<<<(prep_total + 255) / 256, 256>>>(w1, g1, b1, m1, v1,
                                              w2, g2, b2, m2, v2);
    transpose_feat<<<dim3(Nc / 32, CIN / 32, Bc), dim3(32, 8)>>>(feat);
    cylinder_query<<<(Bc * Nc) / 4, 128>>>(xyz, rot);
    tc_mlp<<<Bc * Nc / 4, 256, SMEM_TOTAL>>>(out);
}